// round 14
// baseline (speedup 1.0000x reference)
#include <cuda_runtime.h>
#include <cuda_fp16.h>
#include <math.h>
#include <stdint.h>

// Problem dims
constexpr int Bc = 4, Sc = 2048, Dc = 2048, Hc = 16, HDc = 128;
constexpr int Mc = Bc * Sc;

// Scratch (fp16 everywhere between stages)
__device__ __half g_xh [Mc * Dc];
__device__ __half g_wqh[Dc * Dc];
__device__ __half g_wkh[Dc * Dc];
__device__ __half g_wvh[Dc * Dc];
__device__ __half g_woh[Dc * Dc];
__device__ __half g_Qh [Bc * Hc * Sc * HDc]; // [B,H,S,HD], pre-scaled 1/sqrt(HD)
__device__ __half g_Kh [Bc * Hc * Sc * HDc]; // [B,H,S,HD]
__device__ __half g_Vh [Bc * Hc * Sc * HDc]; // [B,H,HD,S] (TRANSPOSED per head)
__device__ __half g_Oh [Mc * Dc];            // attention output [B,S,D] fp16

// ---------------------------------------------------------------------------
// helpers (sm_103 base target: mma.sync + cp.async + ldmatrix only)
// ---------------------------------------------------------------------------
__device__ __forceinline__ void mma_fp16(float* d, const uint32_t* a, const uint32_t* b) {
    asm volatile(
        "mma.sync.aligned.m16n8k16.row.col.f32.f16.f16.f32 "
        "{%0,%1,%2,%3},{%4,%5,%6,%7},{%8,%9},{%0,%1,%2,%3};"
        : "+f"(d[0]), "+f"(d[1]), "+f"(d[2]), "+f"(d[3])
        : "r"(a[0]), "r"(a[1]), "r"(a[2]), "r"(a[3]), "r"(b[0]), "r"(b[1]));
}

__device__ __forceinline__ void ldsm_x4(uint32_t* r, uint32_t addr) {
    asm volatile("ldmatrix.sync.aligned.m8n8.x4.shared.b16 {%0,%1,%2,%3}, [%4];"
        : "=r"(r[0]), "=r"(r[1]), "=r"(r[2]), "=r"(r[3]) : "r"(addr));
}

__device__ __forceinline__ uint32_t h2u(float x, float y) {
    __half2 h = __float22half2_rn(make_float2(x, y));
    return *(uint32_t*)&h;
}

__device__ __forceinline__ uint32_t smem_u32(const void* p) {
    uint32_t a;
    asm("{ .reg .u64 t; cvta.to.shared.u64 t, %1; cvt.u32.u64 %0, t; }"
        : "=r"(a) : "l"(p));
    return a;
}

#define CP_ASYNC16(dst, src) \
    asm volatile("cp.async.cg.shared.global [%0], [%1], 16;" :: "r"(dst), "l"(src))
#define CP_COMMIT() asm volatile("cp.async.commit_group;" ::: "memory")
#define CP_WAIT1()  asm volatile("cp.async.wait_group 1;" ::: "memory")
#define CP_WAIT0()  asm volatile("cp.async.wait_group 0;" ::: "memory")

// ---------------------------------------------------------------------------
// fp32 -> fp16 conversion: ALL five tensors in ONE launch.
// ---------------------------------------------------------------------------
__global__ void f2h_all(const float* __restrict__ x,  const float* __restrict__ wq,
                        const float* __restrict__ wk, const float* __restrict__ wv,
                        const float* __restrict__ wo,
                        __half* xh, __half* wqh, __half* wkh, __half* wvh, __half* woh)
{
    const int i = blockIdx.x * 256 + threadIdx.x;
    const float* in;
    __half* out;
    int idx;
    if (i < 4194304) {
        in = x; out = xh; idx = i;
    } else {
        const int j = i - 4194304;
        const int r = j >> 20;
        idx = j & 0xFFFFF;
        in  = (r == 0) ? wq  : (r == 1) ? wk  : (r == 2) ? wv  : wo;
        out = (r == 0) ? wqh : (r == 1) ? wkh : (r == 2) ? wvh : woh;
    }
    float4 v = ((const float4*)in)[idx];
    uint2 o;
    o.x = h2u(v.x, v.y);
    o.y = h2u(v.z, v.w);
    ((uint2*)out)[idx] = o;
}

// ---------------------------------------------------------------------------
// GEMM mainloop: CTA 128x128, 4 warps, warp tile 64x64 (4 m-tiles x 8 n-tiles).
// k-depth 32, 3-stage cp.async ring, WAIT1, ldmatrix fragments.
// smem row stride 20 u32 (ldsm banks conflict-free). Data placement and
// k-accumulation order identical to round 11 -> bitwise identical results.
// Per warp per ktile: 64 HMMA, 16 LDSM (MMA:LDSM ratio doubled).
// ---------------------------------------------------------------------------
constexpr int LDSg   = 20;
constexpr int STG_U  = 2 * 128 * LDSg;     // 5120 u32 per stage
constexpr int GSMEMB = 3 * STG_U * 4;      // 61440 B
constexpr int GTHR   = 128;                // 4 warps

__device__ __forceinline__ void gemm_main(const __half* __restrict__ A,
                                          const __half* __restrict__ W,
                                          int bm, int bn,
                                          uint32_t* smu, float (&acc)[4][8][4])
{
    constexpr int Kd = Dc;
    const uint32_t smb = smem_u32(smu);
    const int tid  = threadIdx.x;
    const int wid  = tid >> 5;
    const int lane = tid & 31;
    const int wm   = (wid >> 1) * 64;   // warp row offset: 0 / 64
    const int wn   = (wid & 1) * 64;    // warp col offset: 0 / 64

    auto issue_stage = [&](int s, int kt) {
        const uint32_t so = (uint32_t)(s * STG_U);
        const int ko = kt * 32;
#pragma unroll
        for (int p = 0; p < 4; p++) {
            const int q = tid + p * 128;     // 0..511
            const int row = q >> 2;          // 0..127
            const int c4 = q & 3;            // 16B chunk within 32-half ktile
            CP_ASYNC16(smb + (uint32_t)(so + row * LDSg + c4 * 4) * 4u,
                       A + (size_t)(bm + row) * Kd + ko + c4 * 8);
            CP_ASYNC16(smb + (uint32_t)(so + 2560 + row * LDSg + c4 * 4) * 4u,
                       W + (size_t)(bn + row) * Kd + ko + c4 * 8);
        }
    };

    const uint32_t aoff = (uint32_t)((wm + (lane & 15)) * LDSg
                                     + ((lane >> 4) & 1) * 4) * 4u;
    const uint32_t boff = (uint32_t)((wn + (lane & 7) + (lane >> 4) * 8) * LDSg
                                     + ((lane >> 3) & 1) * 4) * 4u;

#pragma unroll
    for (int mt = 0; mt < 4; mt++)
#pragma unroll
        for (int nt = 0; nt < 8; nt++)
#pragma unroll
            for (int r = 0; r < 4; r++) acc[mt][nt][r] = 0.0f;

    issue_stage(0, 0); CP_COMMIT();
    issue_stage(1, 1); CP_COMMIT();

    constexpr int NKT = Kd / 32;  // 64
    for (int kt = 0; kt < NKT; kt++) {
        const int s = kt % 3;
        CP_WAIT1();
        __syncthreads();
        if (kt + 2 < NKT) issue_stage((kt + 2) % 3, kt + 2);
        CP_COMMIT();

        const uint32_t abase = smb + (uint32_t)(s * STG_U) * 4u + aoff;
        const uint32_t bbase = smb + (uint32_t)(s * STG_U + 2560) * 4u + boff;
#pragma unroll
        for (int ks = 0; ks < 2; ks++) {
            const uint32_t ko = (uint32_t)(ks * 32);
            uint32_t af[4][4];
            ldsm_x4(af[0], abase + ko);
            ldsm_x4(af[1], abase + ko + 1280u);
            ldsm_x4(af[2], abase + ko + 2560u);
            ldsm_x4(af[3], abase + ko + 3840u);
#pragma unroll
            for (int ntb = 0; ntb < 8; ntb += 2) {
                uint32_t bf[4];
                ldsm_x4(bf, bbase + ko + (uint32_t)(ntb * 640));
#pragma unroll
                for (int mt = 0; mt < 4; mt++) {
                    mma_fp16(acc[mt][ntb],     af[mt], bf);
                    mma_fp16(acc[mt][ntb + 1], af[mt], bf + 2);
                }
            }
        }
    }
}

// ---------------------------------------------------------------------------
// Merged Q/K/V projection: blockIdx.z selects weight + epilogue.
// z=0: Q (+RoPE, *1/sqrt(HD)) [B,H,S,HD]; z=1: K (+RoPE) [B,H,S,HD];
// z=2: V transposed [B,H,HD,S].
// ---------------------------------------------------------------------------
__global__ void __launch_bounds__(GTHR, 2)
gemm_qkv(const __half* __restrict__ xh,
         const __half* __restrict__ wqh, const __half* __restrict__ wkh,
         const __half* __restrict__ wvh,
         __half* __restrict__ Qo, __half* __restrict__ Ko, __half* __restrict__ Vo,
         const int* __restrict__ pos)
{
    extern __shared__ uint32_t smu[];
    const int bm = blockIdx.y * 128;
    const int bn = blockIdx.x * 128;
    const int z  = blockIdx.z;
    const __half* W = (z == 0) ? wqh : (z == 1) ? wkh : wvh;

    float acc[4][8][4];
    gemm_main(xh, W, bm, bn, smu, acc);

    const int tid  = threadIdx.x;
    const int wid  = tid >> 5;
    const int lane = tid & 31;
    const int wm   = (wid >> 1) * 64;
    const int wn   = (wid & 1) * 64;
    const int g    = lane >> 2;
    const int t4   = lane & 3;

    const float qscale = 0.08838834764831845f;  // 1/sqrt(128)
    __half* oh = (z == 0) ? Qo : (z == 1) ? Ko : Vo;

#pragma unroll
    for (int nt = 0; nt < 8; nt++) {
        const int col = bn + wn + nt * 8 + 2 * t4;
        const int h  = col >> 7;
        const int hd = col & 127;
        float invf = 0.0f;
        if (z <= 1)
            invf = (float)exp2(-(double)hd * (13.287712379549449 / 128.0));
#pragma unroll
        for (int mt = 0; mt < 4; mt++) {
#pragma unroll
            for (int rr = 0; rr < 2; rr++) {
                const int m = bm + wm + mt * 16 + g + rr * 8;
                const int b = m >> 11;
                const int s = m & 2047;
                float x1 = acc[mt][nt][rr * 2];
                float x2 = acc[mt][nt][rr * 2 + 1];
                if (z <= 1) {
                    const float ang = (float)pos[s] * invf;
                    float sn, cs;
                    sincosf(ang, &sn, &cs);
                    float r1 = x1 * cs - x2 * sn;
                    float r2 = x1 * sn + x2 * cs;
                    if (z == 0) { r1 *= qscale; r2 *= qscale; }
                    *(uint32_t*)&oh[(((size_t)b * Hc + h) * Sc + s) * HDc + hd] =
                        h2u(r1, r2);
                } else {
                    const size_t base = ((size_t)b * Hc + h) * HDc;
                    oh[(base + hd)     * Sc + s] = __float2half_rn(x1);
                    oh[(base + hd + 1) * Sc + s] = __float2half_rn(x2);
                }
            }
        }
    }
}

// ---------------------------------------------------------------------------
// Output projection: out[M,N] fp32 = O_fp16 * wo^T
// ---------------------------------------------------------------------------
__global__ void __launch_bounds__(GTHR, 2)
gemm_out(const __half* __restrict__ Oh, const __half* __restrict__ woh,
         float* __restrict__ out)
{
    extern __shared__ uint32_t smu[];
    const int bm = blockIdx.y * 128;
    const int bn = blockIdx.x * 128;

    float acc[4][8][4];
    gemm_main(Oh, woh, bm, bn, smu, acc);

    const int tid  = threadIdx.x;
    const int wid  = tid >> 5;
    const int lane = tid & 31;
    const int wm   = (wid >> 1) * 64;
    const int wn   = (wid & 1) * 64;
    const int g    = lane >> 2;
    const int t4   = lane & 3;

#pragma unroll
    for (int nt = 0; nt < 8; nt++) {
        const int col = bn + wn + nt * 8 + 2 * t4;
#pragma unroll
        for (int mt = 0; mt < 4; mt++) {
            const int r0 = bm + wm + mt * 16 + g;
            *(float2*)&out[(size_t)r0 * Dc + col] =
                make_float2(acc[mt][nt][0], acc[mt][nt][1]);
            *(float2*)&out[(size_t)(r0 + 8) * Dc + col] =
                make_float2(acc[mt][nt][2], acc[mt][nt][3]);
        }
    }
}

// ---------------------------------------------------------------------------
// Flash attention (causal), fp16 m16n8k16, cp.async 2-stage K/V.
// Register-resident P + ldmatrix B-fragments (round-11 proven, unchanged).
// ---------------------------------------------------------------------------
constexpr int KSTG_U    = 8960;
constexpr int VOFF_U    = 4352;
constexpr int ATT_SMEMB = 2 * KSTG_U * 4;   // 71680 B

__global__ void __launch_bounds__(256, 1)
attn_mma(const __half* __restrict__ Q, const __half* __restrict__ K,
         const __half* __restrict__ V, __half* __restrict__ O)
{
    extern __shared__ uint32_t smu[];
    const uint32_t smb = smem_u32(smu);

    const int tid  = threadIdx.x;
    const int wid  = tid >> 5;
    const int lane = tid & 31;
    const int g    = lane >> 2;
    const int t4   = lane & 3;
    const int qb   = (gridDim.x - 1) - blockIdx.x;   // heavy blocks first
    const int bh   = blockIdx.y;
    const int q0   = qb * 128;
    const size_t hoff = (size_t)bh * (size_t)(Sc * HDc);
    const int rowb = wid * 16;

    const int ntL  = lane >> 4;
    const int kbL  = (lane >> 3) & 1;
    const int rowL = lane & 7;
    const uint32_t koffL = (uint32_t)((ntL * 8 + rowL) * 68 + 4 * kbL) * 4u;
    const uint32_t voffL = (uint32_t)((ntL * 8 + rowL) * 36 + 4 * kbL) * 4u;

    {
        const __half* Qg = Q + hoff + (size_t)q0 * HDc;
#pragma unroll
        for (int p = 0; p < 8; p++) {
            int q = tid + p * 256;
            int row = q >> 4;
            int c4 = q & 15;
            CP_ASYNC16(smb + (uint32_t)(row * 68 + c4 * 4) * 4u,
                       Qg + (size_t)row * HDc + c4 * 8);
        }
        CP_COMMIT();
        CP_WAIT0();
    }
    __syncthreads();

    uint32_t qf[8][4];
#pragma unroll
    for (int ks = 0; ks < 8; ks++) {
        const int r0 = (rowb + g) * 68 + 8 * ks + t4;
        const int r1 = r0 + 8 * 68;
        qf[ks][0] = smu[r0];
        qf[ks][1] = smu[r1];
        qf[ks][2] = smu[r0 + 4];
        qf[ks][3] = smu[r1 + 4];
    }
    __syncthreads();

    const int nkb = 2 * qb + 2;

    auto issue = [&](int kb) {
        const int s = kb & 1;
        const __half* Kg = K + hoff + (size_t)(kb * 64) * HDc;
        const __half* Vg = V + hoff + (size_t)kb * 64;
        const uint32_t kbase = smb + (uint32_t)(s * KSTG_U) * 4u;
        const uint32_t vbase = kbase + (uint32_t)VOFF_U * 4u;
#pragma unroll
        for (int p = 0; p < 4; p++) {
            int q = tid + p * 256;
            int row = q >> 4;
            int c4 = q & 15;
            CP_ASYNC16(kbase + (uint32_t)(row * 68 + c4 * 4) * 4u,
                       Kg + (size_t)row * HDc + c4 * 8);
        }
#pragma unroll
        for (int p = 0; p < 4; p++) {
            int q = tid + p * 256;
            int row = q >> 3;
            int c4 = q & 7;
            CP_ASYNC16(vbase + (uint32_t)(row * 36 + c4 * 4) * 4u,
                       Vg + (size_t)row * Sc + c4 * 8);
        }
    };

    float accO[16][4];
#pragma unroll
    for (int nt = 0; nt < 16; nt++)
#pragma unroll
        for (int r = 0; r < 4; r++) accO[nt][r] = 0.0f;
    float m0 = -1e30f, m1 = -1e30f, l0 = 0.0f, l1 = 0.0f;

    issue(0); CP_COMMIT();
    if (nkb > 1) issue(1);
    CP_COMMIT();

    for (int kb = 0; kb < nkb; kb++) {
        CP_WAIT1();
        __syncthreads();
        const uint32_t kbase_b = smb + (uint32_t)((kb & 1) * KSTG_U) * 4u;
        const uint32_t vbase_b = kbase_b + (uint32_t)VOFF_U * 4u;

        float s[8][4];
#pragma unroll
        for (int nt = 0; nt < 8; nt++)
#pragma unroll
            for (int r = 0; r < 4; r++) s[nt][r] = 0.0f;

#pragma unroll
        for (int ks_ = 0; ks_ < 8; ks_++) {
#pragma unroll
            for (int ntb = 0; ntb < 8; ntb += 2) {
                uint32_t kf[4];
                ldsm_x4(kf, kbase_b + koffL + (uint32_t)(ntb * 8 * 68 + 8 * ks_) * 4u);
                mma_fp16(s[ntb],     qf[ks_], kf);
                mma_fp16(s[ntb + 1], qf[ks_], kf + 2);
            }
        }

        if (kb >= 2 * qb) {
            const int colb = kb * 64 + 2 * t4;
            const int row0 = q0 + rowb + g;
#pragma unroll
            for (int nt = 0; nt < 8; nt++) {
                const int c0 = colb + nt * 8;
                if (c0     > row0)     s[nt][0] = -1e30f;
                if (c0 + 1 > row0)     s[nt][1] = -1e30f;
                if (c0     > row0 + 8) s[nt][2] = -1e30f;
                if (c0 + 1 > row0 + 8) s[nt][3] = -1e30f;
            }
        }

        float bm0 = -1e30f, bm1 = -1e30f;
#pragma unroll
        for (int nt = 0; nt < 8; nt++) {
            bm0 = fmaxf(bm0, fmaxf(s[nt][0], s[nt][1]));
            bm1 = fmaxf(bm1, fmaxf(s[nt][2], s[nt][3]));
        }
        bm0 = fmaxf(bm0, __shfl_xor_sync(0xffffffffu, bm0, 1));
        bm0 = fmaxf(bm0, __shfl_xor_sync(0xffffffffu, bm0, 2));
        bm1 = fmaxf(bm1, __shfl_xor_sync(0xffffffffu, bm1, 1));
        bm1 = fmaxf(bm1, __shfl_xor_sync(0xffffffffu, bm1, 2));
        const float nm0 = fmaxf(m0, bm0);
        const float nm1 = fmaxf(m1, bm1);
        const float f0 = __expf(m0 - nm0);
        const float f1 = __expf(m1 - nm1);
        float ps0 = 0.0f, ps1 = 0.0f;
        uint32_t pf[8][2];
#pragma unroll
        for (int nt = 0; nt < 8; nt++) {
            float p0 = __expf(s[nt][0] - nm0);
            float p1 = __expf(s[nt][1] - nm0);
            float p2 = __expf(s[nt][2] - nm1);
            float p3 = __expf(s[nt][3] - nm1);
            ps0 += p0 + p1;
            ps1 += p2 + p3;
            pf[nt][0] = h2u(p0, p1);
            pf[nt][1] = h2u(p2, p3);
        }
        ps0 += __shfl_xor_sync(0xffffffffu, ps0, 1);
        ps0 += __shfl_xor_sync(0xffffffffu, ps0, 2);
        ps1 += __shfl_xor_sync(0xffffffffu, ps1, 1);
        ps1 += __shfl_xor_sync(0xffffffffu, ps1, 2);
        l0 = l0 * f0 + ps0;
        l1 = l1 * f1 + ps1;
        m0 = nm0;
        m1 = nm1;
#pragma unroll
        for (int nt = 0; nt < 16; nt++) {
            accO[nt][0] *= f0; accO[nt][1] *= f0;
            accO[nt][2] *= f1; accO[nt][3] *= f1;
        }

#pragma unroll
        for (int ks_ = 0; ks_ < 4; ks_++) {
            uint32_t a[4];
            a[0] = pf[2 * ks_][0];
            a[1] = pf[2 * ks_][1];
            a[2] = pf[2 * ks_ + 1][0];
            a[3] = pf[2 * ks_ + 1][1];
#pragma unroll
            for (int ntb = 0; ntb < 16; ntb += 2) {
                uint32_t vf[4];
                ldsm_x4(vf, vbase_b + voffL + (uint32_t)(ntb * 8 * 36 + 8 * ks_) * 4u);
                mma_fp16(accO[ntb],     a, vf);
                mma_fp16(accO[ntb + 1], a, vf + 2);
            }
        }
        __syncthreads();
        if (kb + 2 < nkb) issue(kb + 2);
        CP_COMMIT();
    }

    const int b_ = bh >> 4;
    const int h_ = bh & 15;
    const float inv0 = 1.0f / l0;
    const float inv1 = 1.0f / l1;
    const int r0g = q0 + rowb + g;
    __half* Op0 = O + ((size_t)b_ * Sc + r0g) * Dc + h_ * HDc;
    __half* Op1 = Op0 + (size_t)8 * Dc;
#pragma unroll
    for (int nt = 0; nt < 16; nt++) {
        const int cc = nt * 8 + 2 * t4;
        *(uint32_t*)&Op0[cc] = h2u(accO[nt][0] * inv0, accO[nt][1] * inv0);
        *(uint32_t*)&Op1[cc] = h2u(accO[nt][2] * inv1, accO[nt][3] * inv1);
    }
}

// ---------------------------------------------------------------------------
extern "C" void kernel_launch(void* const* d_in, const int* in_sizes, int n_in,
                              void* d_out, int out_size)
{
    const float* x  = (const float*)d_in[0];
    const float* wq = (const float*)d_in[1];
    const float* wk = (const float*)d_in[2];
    const float* wv = (const float*)d_in[3];
    const float* wo = (const float*)d_in[4];
    const int* pos  = (const int*)d_in[5];

    __half *xh, *wqh, *wkh, *wvh, *woh, *q, *k, *v, *oh;
    cudaGetSymbolAddress((void**)&xh,  g_xh);
    cudaGetSymbolAddress((void**)&wqh, g_wqh);
    cudaGetSymbolAddress((void**)&wkh, g_wkh);
    cudaGetSymbolAddress((void**)&wvh, g_wvh);
    cudaGetSymbolAddress((void**)&woh, g_woh);
    cudaGetSymbolAddress((void**)&q,   g_Qh);
    cudaGetSymbolAddress((void**)&k,   g_Kh);
    cudaGetSymbolAddress((void**)&v,   g_Vh);
    cudaGetSymbolAddress((void**)&oh,  g_Oh);

    // One launch converts all five fp32 tensors to fp16
    f2h_all<<<32768, 256>>>(x, wq, wk, wv, wo, xh, wqh, wkh, wvh, woh);

    cudaFuncSetAttribute(gemm_qkv, cudaFuncAttributeMaxDynamicSharedMemorySize, GSMEMB);
    cudaFuncSetAttribute(gemm_out, cudaFuncAttributeMaxDynamicSharedMemorySize, GSMEMB);
    cudaFuncSetAttribute(attn_mma, cudaFuncAttributeMaxDynamicSharedMemorySize, ATT_SMEMB);

    // Merged Q/K/V projections: one launch, grid.z selects weight/epilogue
    gemm_qkv<<<dim3(Dc / 128, Mc / 128, 3), GTHR, GSMEMB>>>(
        xh, wqh, wkh, wvh, q, k, v, pos);

    attn_mma<<<dim3(Sc / 128, Bc * Hc), 256, ATT_SMEMB>>>(q, k, v, oh);

    gemm_out<<<dim3(Dc / 128, Mc / 128), GTHR, GSMEMB>>>(oh, woh, (float*)d_out);
}

// round 15
// speedup vs baseline: 1.0520x; 1.0520x over previous
#include <cuda_runtime.h>
#include <cuda_fp16.h>
#include <math.h>
#include <stdint.h>

// Problem dims
constexpr int Bc = 4, Sc = 2048, Dc = 2048, Hc = 16, HDc = 128;
constexpr int Mc = Bc * Sc;

// Scratch (fp16 everywhere between stages)
__device__ __half g_xh [Mc * Dc];
__device__ __half g_wqh[Dc * Dc];
__device__ __half g_wkh[Dc * Dc];
__device__ __half g_wvh[Dc * Dc];
__device__ __half g_woh[Dc * Dc];
__device__ __half g_Qh [Bc * Hc * Sc * HDc]; // [B,H,S,HD], pre-scaled 1/sqrt(HD)
__device__ __half g_Kh [Bc * Hc * Sc * HDc]; // [B,H,S,HD]
__device__ __half g_Vh [Bc * Hc * Sc * HDc]; // [B,H,HD,S] (TRANSPOSED per head)
__device__ __half g_Oh [Mc * Dc];            // attention output [B,S,D] fp16

// ---------------------------------------------------------------------------
// helpers
// ---------------------------------------------------------------------------
__device__ __forceinline__ void mma_fp16(float* d, const uint32_t* a, const uint32_t* b) {
    asm volatile(
        "mma.sync.aligned.m16n8k16.row.col.f32.f16.f16.f32 "
        "{%0,%1,%2,%3},{%4,%5,%6,%7},{%8,%9},{%0,%1,%2,%3};"
        : "+f"(d[0]), "+f"(d[1]), "+f"(d[2]), "+f"(d[3])
        : "r"(a[0]), "r"(a[1]), "r"(a[2]), "r"(a[3]), "r"(b[0]), "r"(b[1]));
}

__device__ __forceinline__ void ldsm_x4(uint32_t* r, uint32_t addr) {
    asm volatile("ldmatrix.sync.aligned.m8n8.x4.shared.b16 {%0,%1,%2,%3}, [%4];"
        : "=r"(r[0]), "=r"(r[1]), "=r"(r[2]), "=r"(r[3]) : "r"(addr));
}

__device__ __forceinline__ uint32_t h2u(float x, float y) {
    __half2 h = __float22half2_rn(make_float2(x, y));
    return *(uint32_t*)&h;
}

__device__ __forceinline__ uint32_t smem_u32(const void* p) {
    uint32_t a;
    asm("{ .reg .u64 t; cvta.to.shared.u64 t, %1; cvt.u32.u64 %0, t; }"
        : "=r"(a) : "l"(p));
    return a;
}

#define CP_ASYNC16(dst, src) \
    asm volatile("cp.async.cg.shared.global [%0], [%1], 16;" :: "r"(dst), "l"(src))
#define CP_COMMIT() asm volatile("cp.async.commit_group;" ::: "memory")
#define CP_WAIT1()  asm volatile("cp.async.wait_group 1;" ::: "memory")
#define CP_WAIT0()  asm volatile("cp.async.wait_group 0;" ::: "memory")

// ---------------------------------------------------------------------------
// fp32 -> fp16 conversion: ALL five tensors in ONE launch.
// ---------------------------------------------------------------------------
__global__ void f2h_all(const float* __restrict__ x,  const float* __restrict__ wq,
                        const float* __restrict__ wk, const float* __restrict__ wv,
                        const float* __restrict__ wo,
                        __half* xh, __half* wqh, __half* wkh, __half* wvh, __half* woh)
{
    const int i = blockIdx.x * 256 + threadIdx.x;
    const float* in;
    __half* out;
    int idx;
    if (i < 4194304) {
        in = x; out = xh; idx = i;
    } else {
        const int j = i - 4194304;
        const int r = j >> 20;
        idx = j & 0xFFFFF;
        in  = (r == 0) ? wq  : (r == 1) ? wk  : (r == 2) ? wv  : wo;
        out = (r == 0) ? wqh : (r == 1) ? wkh : (r == 2) ? wvh : woh;
    }
    float4 v = ((const float4*)in)[idx];
    uint2 o;
    o.x = h2u(v.x, v.y);
    o.y = h2u(v.z, v.w);
    ((uint2*)out)[idx] = o;
}

// ---------------------------------------------------------------------------
// Shared GEMM constants: CTA 128x128, k-depth 32, 3-stage cp.async ring.
// smem row stride 20 u32 (ldsm banks conflict-free).
// ---------------------------------------------------------------------------
constexpr int LDSg   = 20;
constexpr int STG_U  = 2 * 128 * LDSg;     // 5120 u32 per stage
constexpr int GSMEMB = 3 * STG_U * 4;      // 61440 B

// ---------------------------------------------------------------------------
// Mainloop A (round-13 proven): 8 warps / 256 threads, warp tile 64x32.
// Epilogue-light register footprint -> used by the RoPE/scatter QKV kernel.
// ---------------------------------------------------------------------------
__device__ __forceinline__ void gemm_main8(const __half* __restrict__ A,
                                           const __half* __restrict__ W,
                                           int bm, int bn,
                                           uint32_t* smu, float (&acc)[4][4][4])
{
    constexpr int Kd = Dc;
    const uint32_t smb = smem_u32(smu);
    const int tid  = threadIdx.x;
    const int wid  = tid >> 5;
    const int lane = tid & 31;
    const int wm   = (wid >> 2) * 64;
    const int wn   = (wid & 3) * 32;

    const int lrow = tid >> 2;               // 0..63
    const int lc4  = tid & 3;                // 0..3
    const __half* Ag = A + (size_t)(bm + lrow) * Kd + lc4 * 8;
    const __half* Wg = W + (size_t)(bn + lrow) * Kd + lc4 * 8;
    const uint32_t dstA = (uint32_t)(lrow * LDSg + lc4 * 4);

    auto issue_stage = [&](int s, int kt) {
        const uint32_t so = (uint32_t)(s * STG_U);
        const int ko = kt * 32;
        CP_ASYNC16(smb + (so + dstA) * 4u,                    Ag + ko);
        CP_ASYNC16(smb + (so + dstA + 64 * LDSg) * 4u,        Ag + (size_t)64 * Kd + ko);
        CP_ASYNC16(smb + (so + 2560 + dstA) * 4u,             Wg + ko);
        CP_ASYNC16(smb + (so + 2560 + dstA + 64 * LDSg) * 4u, Wg + (size_t)64 * Kd + ko);
    };

    const uint32_t aoff = (uint32_t)((wm + (lane & 7) + ((lane >> 3) & 1) * 8) * LDSg
                                     + ((lane >> 4) & 1) * 4) * 4u;
    const uint32_t boff = (uint32_t)((wn + (lane & 7) + (lane >> 4) * 8) * LDSg
                                     + ((lane >> 3) & 1) * 4) * 4u;

#pragma unroll
    for (int mt = 0; mt < 4; mt++)
#pragma unroll
        for (int nt = 0; nt < 4; nt++)
#pragma unroll
            for (int r = 0; r < 4; r++) acc[mt][nt][r] = 0.0f;

    issue_stage(0, 0); CP_COMMIT();
    issue_stage(1, 1); CP_COMMIT();

    constexpr int NKT = Kd / 32;  // 64
    for (int kt = 0; kt < NKT; kt++) {
        const int s = kt % 3;
        CP_WAIT1();
        __syncthreads();
        if (kt + 2 < NKT) issue_stage((kt + 2) % 3, kt + 2);
        CP_COMMIT();

        const uint32_t abase = smb + (uint32_t)(s * STG_U) * 4u + aoff;
        const uint32_t bbase = smb + (uint32_t)(s * STG_U + 2560) * 4u + boff;
#pragma unroll
        for (int ks = 0; ks < 2; ks++) {
            const uint32_t ko = (uint32_t)(ks * 32);
            uint32_t af[4][4], bf0[4], bf1[4];
            ldsm_x4(af[0], abase + ko);
            ldsm_x4(af[1], abase + ko + 1280u);
            ldsm_x4(af[2], abase + ko + 2560u);
            ldsm_x4(af[3], abase + ko + 3840u);
            ldsm_x4(bf0, bbase + ko);
            ldsm_x4(bf1, bbase + ko + 1280u);
#pragma unroll
            for (int mt = 0; mt < 4; mt++) {
                mma_fp16(acc[mt][0], af[mt], bf0);
                mma_fp16(acc[mt][1], af[mt], bf0 + 2);
                mma_fp16(acc[mt][2], af[mt], bf1);
                mma_fp16(acc[mt][3], af[mt], bf1 + 2);
            }
        }
    }
}

// ---------------------------------------------------------------------------
// Mainloop B (round-14, better tensor util): 4 warps / 128 threads,
// warp tile 64x64. Used by gemm_out (trivial epilogue fits registers).
// ---------------------------------------------------------------------------
__device__ __forceinline__ void gemm_main4(const __half* __restrict__ A,
                                           const __half* __restrict__ W,
                                           int bm, int bn,
                                           uint32_t* smu, float (&acc)[4][8][4])
{
    constexpr int Kd = Dc;
    const uint32_t smb = smem_u32(smu);
    const int tid  = threadIdx.x;
    const int wid  = tid >> 5;
    const int lane = tid & 31;
    const int wm   = (wid >> 1) * 64;
    const int wn   = (wid & 1) * 64;

    auto issue_stage = [&](int s, int kt) {
        const uint32_t so = (uint32_t)(s * STG_U);
        const int ko = kt * 32;
#pragma unroll
        for (int p = 0; p < 4; p++) {
            const int q = tid + p * 128;
            const int row = q >> 2;
            const int c4 = q & 3;
            CP_ASYNC16(smb + (uint32_t)(so + row * LDSg + c4 * 4) * 4u,
                       A + (size_t)(bm + row) * Kd + ko + c4 * 8);
            CP_ASYNC16(smb + (uint32_t)(so + 2560 + row * LDSg + c4 * 4) * 4u,
                       W + (size_t)(bn + row) * Kd + ko + c4 * 8);
        }
    };

    const uint32_t aoff = (uint32_t)((wm + (lane & 15)) * LDSg
                                     + ((lane >> 4) & 1) * 4) * 4u;
    const uint32_t boff = (uint32_t)((wn + (lane & 7) + (lane >> 4) * 8) * LDSg
                                     + ((lane >> 3) & 1) * 4) * 4u;

#pragma unroll
    for (int mt = 0; mt < 4; mt++)
#pragma unroll
        for (int nt = 0; nt < 8; nt++)
#pragma unroll
            for (int r = 0; r < 4; r++) acc[mt][nt][r] = 0.0f;

    issue_stage(0, 0); CP_COMMIT();
    issue_stage(1, 1); CP_COMMIT();

    constexpr int NKT = Kd / 32;  // 64
    for (int kt = 0; kt < NKT; kt++) {
        const int s = kt % 3;
        CP_WAIT1();
        __syncthreads();
        if (kt + 2 < NKT) issue_stage((kt + 2) % 3, kt + 2);
        CP_COMMIT();

        const uint32_t abase = smb + (uint32_t)(s * STG_U) * 4u + aoff;
        const uint32_t bbase = smb + (uint32_t)(s * STG_U + 2560) * 4u + boff;
#pragma unroll
        for (int ks = 0; ks < 2; ks++) {
            const uint32_t ko = (uint32_t)(ks * 32);
            uint32_t af[4][4];
            ldsm_x4(af[0], abase + ko);
            ldsm_x4(af[1], abase + ko + 1280u);
            ldsm_x4(af[2], abase + ko + 2560u);
            ldsm_x4(af[3], abase + ko + 3840u);
#pragma unroll
            for (int ntb = 0; ntb < 8; ntb += 2) {
                uint32_t bf[4];
                ldsm_x4(bf, bbase + ko + (uint32_t)(ntb * 640));
#pragma unroll
                for (int mt = 0; mt < 4; mt++) {
                    mma_fp16(acc[mt][ntb],     af[mt], bf);
                    mma_fp16(acc[mt][ntb + 1], af[mt], bf + 2);
                }
            }
        }
    }
}

// ---------------------------------------------------------------------------
// Merged Q/K/V projection (256 threads, round-13 form).
// z=0: Q (+RoPE, *1/sqrt(HD)) [B,H,S,HD]; z=1: K (+RoPE) [B,H,S,HD];
// z=2: V transposed [B,H,HD,S].
// ---------------------------------------------------------------------------
__global__ void __launch_bounds__(256, 2)
gemm_qkv(const __half* __restrict__ xh,
         const __half* __restrict__ wqh, const __half* __restrict__ wkh,
         const __half* __restrict__ wvh,
         __half* __restrict__ Qo, __half* __restrict__ Ko, __half* __restrict__ Vo,
         const int* __restrict__ pos)
{
    extern __shared__ uint32_t smu[];
    const int bm = blockIdx.y * 128;
    const int bn = blockIdx.x * 128;
    const int z  = blockIdx.z;
    const __half* W = (z == 0) ? wqh : (z == 1) ? wkh : wvh;

    float acc[4][4][4];
    gemm_main8(xh, W, bm, bn, smu, acc);

    const int tid  = threadIdx.x;
    const int wid  = tid >> 5;
    const int lane = tid & 31;
    const int wm   = (wid >> 2) * 64;
    const int wn   = (wid & 3) * 32;
    const int g    = lane >> 2;
    const int t4   = lane & 3;

    const float qscale = 0.08838834764831845f;  // 1/sqrt(128)
    __half* oh = (z == 0) ? Qo : (z == 1) ? Ko : Vo;

#pragma unroll
    for (int nt = 0; nt < 4; nt++) {
        const int col = bn + wn + nt * 8 + 2 * t4;
        const int h  = col >> 7;
        const int hd = col & 127;
        float invf = 0.0f;
        if (z <= 1)
            invf = (float)exp2(-(double)hd * (13.287712379549449 / 128.0));
#pragma unroll
        for (int mt = 0; mt < 4; mt++) {
#pragma unroll
            for (int rr = 0; rr < 2; rr++) {
                const int m = bm + wm + mt * 16 + g + rr * 8;
                const int b = m >> 11;
                const int s = m & 2047;
                float x1 = acc[mt][nt][rr * 2];
                float x2 = acc[mt][nt][rr * 2 + 1];
                if (z <= 1) {
                    const float ang = (float)pos[s] * invf;
                    float sn, cs;
                    sincosf(ang, &sn, &cs);
                    float r1 = x1 * cs - x2 * sn;
                    float r2 = x1 * sn + x2 * cs;
                    if (z == 0) { r1 *= qscale; r2 *= qscale; }
                    *(uint32_t*)&oh[(((size_t)b * Hc + h) * Sc + s) * HDc + hd] =
                        h2u(r1, r2);
                } else {
                    const size_t base = ((size_t)b * Hc + h) * HDc;
                    oh[(base + hd)     * Sc + s] = __float2half_rn(x1);
                    oh[(base + hd + 1) * Sc + s] = __float2half_rn(x2);
                }
            }
        }
    }
}

// ---------------------------------------------------------------------------
// Output projection (128 threads, 64x64 warp tiles): out fp32 = O * wo^T
// ---------------------------------------------------------------------------
__global__ void __launch_bounds__(128, 2)
gemm_out(const __half* __restrict__ Oh, const __half* __restrict__ woh,
         float* __restrict__ out)
{
    extern __shared__ uint32_t smu[];
    const int bm = blockIdx.y * 128;
    const int bn = blockIdx.x * 128;

    float acc[4][8][4];
    gemm_main4(Oh, woh, bm, bn, smu, acc);

    const int tid  = threadIdx.x;
    const int wid  = tid >> 5;
    const int lane = tid & 31;
    const int wm   = (wid >> 1) * 64;
    const int wn   = (wid & 1) * 64;
    const int g    = lane >> 2;
    const int t4   = lane & 3;

#pragma unroll
    for (int nt = 0; nt < 8; nt++) {
        const int col = bn + wn + nt * 8 + 2 * t4;
#pragma unroll
        for (int mt = 0; mt < 4; mt++) {
            const int r0 = bm + wm + mt * 16 + g;
            *(float2*)&out[(size_t)r0 * Dc + col] =
                make_float2(acc[mt][nt][0], acc[mt][nt][1]);
            *(float2*)&out[(size_t)(r0 + 8) * Dc + col] =
                make_float2(acc[mt][nt][2], acc[mt][nt][3]);
        }
    }
}

// ---------------------------------------------------------------------------
// Flash attention (causal), fp16 m16n8k16, cp.async 2-stage K/V.
// Register-resident P + ldmatrix B-fragments (round-11 proven, unchanged).
// ---------------------------------------------------------------------------
constexpr int KSTG_U    = 8960;
constexpr int VOFF_U    = 4352;
constexpr int ATT_SMEMB = 2 * KSTG_U * 4;   // 71680 B

__global__ void __launch_bounds__(256, 1)
attn_mma(const __half* __restrict__ Q, const __half* __restrict__ K,
         const __half* __restrict__ V, __half* __restrict__ O)
{
    extern __shared__ uint32_t smu[];
    const uint32_t smb = smem_u32(smu);

    const int tid  = threadIdx.x;
    const int wid  = tid >> 5;
    const int lane = tid & 31;
    const int g    = lane >> 2;
    const int t4   = lane & 3;
    const int qb   = (gridDim.x - 1) - blockIdx.x;   // heavy blocks first
    const int bh   = blockIdx.y;
    const int q0   = qb * 128;
    const size_t hoff = (size_t)bh * (size_t)(Sc * HDc);
    const int rowb = wid * 16;

    const int ntL  = lane >> 4;
    const int kbL  = (lane >> 3) & 1;
    const int rowL = lane & 7;
    const uint32_t koffL = (uint32_t)((ntL * 8 + rowL) * 68 + 4 * kbL) * 4u;
    const uint32_t voffL = (uint32_t)((ntL * 8 + rowL) * 36 + 4 * kbL) * 4u;

    {
        const __half* Qg = Q + hoff + (size_t)q0 * HDc;
#pragma unroll
        for (int p = 0; p < 8; p++) {
            int q = tid + p * 256;
            int row = q >> 4;
            int c4 = q & 15;
            CP_ASYNC16(smb + (uint32_t)(row * 68 + c4 * 4) * 4u,
                       Qg + (size_t)row * HDc + c4 * 8);
        }
        CP_COMMIT();
        CP_WAIT0();
    }
    __syncthreads();

    uint32_t qf[8][4];
#pragma unroll
    for (int ks = 0; ks < 8; ks++) {
        const int r0 = (rowb + g) * 68 + 8 * ks + t4;
        const int r1 = r0 + 8 * 68;
        qf[ks][0] = smu[r0];
        qf[ks][1] = smu[r1];
        qf[ks][2] = smu[r0 + 4];
        qf[ks][3] = smu[r1 + 4];
    }
    __syncthreads();

    const int nkb = 2 * qb + 2;

    auto issue = [&](int kb) {
        const int s = kb & 1;
        const __half* Kg = K + hoff + (size_t)(kb * 64) * HDc;
        const __half* Vg = V + hoff + (size_t)kb * 64;
        const uint32_t kbase = smb + (uint32_t)(s * KSTG_U) * 4u;
        const uint32_t vbase = kbase + (uint32_t)VOFF_U * 4u;
#pragma unroll
        for (int p = 0; p < 4; p++) {
            int q = tid + p * 256;
            int row = q >> 4;
            int c4 = q & 15;
            CP_ASYNC16(kbase + (uint32_t)(row * 68 + c4 * 4) * 4u,
                       Kg + (size_t)row * HDc + c4 * 8);
        }
#pragma unroll
        for (int p = 0; p < 4; p++) {
            int q = tid + p * 256;
            int row = q >> 3;
            int c4 = q & 7;
            CP_ASYNC16(vbase + (uint32_t)(row * 36 + c4 * 4) * 4u,
                       Vg + (size_t)row * Sc + c4 * 8);
        }
    };

    float accO[16][4];
#pragma unroll
    for (int nt = 0; nt < 16; nt++)
#pragma unroll
        for (int r = 0; r < 4; r++) accO[nt][r] = 0.0f;
    float m0 = -1e30f, m1 = -1e30f, l0 = 0.0f, l1 = 0.0f;

    issue(0); CP_COMMIT();
    if (nkb > 1) issue(1);
    CP_COMMIT();

    for (int kb = 0; kb < nkb; kb++) {
        CP_WAIT1();
        __syncthreads();
        const uint32_t kbase_b = smb + (uint32_t)((kb & 1) * KSTG_U) * 4u;
        const uint32_t vbase_b = kbase_b + (uint32_t)VOFF_U * 4u;

        float s[8][4];
#pragma unroll
        for (int nt = 0; nt < 8; nt++)
#pragma unroll
            for (int r = 0; r < 4; r++) s[nt][r] = 0.0f;

#pragma unroll
        for (int ks_ = 0; ks_ < 8; ks_++) {
#pragma unroll
            for (int ntb = 0; ntb < 8; ntb += 2) {
                uint32_t kf[4];
                ldsm_x4(kf, kbase_b + koffL + (uint32_t)(ntb * 8 * 68 + 8 * ks_) * 4u);
                mma_fp16(s[ntb],     qf[ks_], kf);
                mma_fp16(s[ntb + 1], qf[ks_], kf + 2);
            }
        }

        if (kb >= 2 * qb) {
            const int colb = kb * 64 + 2 * t4;
            const int row0 = q0 + rowb + g;
#pragma unroll
            for (int nt = 0; nt < 8; nt++) {
                const int c0 = colb + nt * 8;
                if (c0     > row0)     s[nt][0] = -1e30f;
                if (c0 + 1 > row0)     s[nt][1] = -1e30f;
                if (c0     > row0 + 8) s[nt][2] = -1e30f;
                if (c0 + 1 > row0 + 8) s[nt][3] = -1e30f;
            }
        }

        float bm0 = -1e30f, bm1 = -1e30f;
#pragma unroll
        for (int nt = 0; nt < 8; nt++) {
            bm0 = fmaxf(bm0, fmaxf(s[nt][0], s[nt][1]));
            bm1 = fmaxf(bm1, fmaxf(s[nt][2], s[nt][3]));
        }
        bm0 = fmaxf(bm0, __shfl_xor_sync(0xffffffffu, bm0, 1));
        bm0 = fmaxf(bm0, __shfl_xor_sync(0xffffffffu, bm0, 2));
        bm1 = fmaxf(bm1, __shfl_xor_sync(0xffffffffu, bm1, 1));
        bm1 = fmaxf(bm1, __shfl_xor_sync(0xffffffffu, bm1, 2));
        const float nm0 = fmaxf(m0, bm0);
        const float nm1 = fmaxf(m1, bm1);
        const float f0 = __expf(m0 - nm0);
        const float f1 = __expf(m1 - nm1);
        float ps0 = 0.0f, ps1 = 0.0f;
        uint32_t pf[8][2];
#pragma unroll
        for (int nt = 0; nt < 8; nt++) {
            float p0 = __expf(s[nt][0] - nm0);
            float p1 = __expf(s[nt][1] - nm0);
            float p2 = __expf(s[nt][2] - nm1);
            float p3 = __expf(s[nt][3] - nm1);
            ps0 += p0 + p1;
            ps1 += p2 + p3;
            pf[nt][0] = h2u(p0, p1);
            pf[nt][1] = h2u(p2, p3);
        }
        ps0 += __shfl_xor_sync(0xffffffffu, ps0, 1);
        ps0 += __shfl_xor_sync(0xffffffffu, ps0, 2);
        ps1 += __shfl_xor_sync(0xffffffffu, ps1, 1);
        ps1 += __shfl_xor_sync(0xffffffffu, ps1, 2);
        l0 = l0 * f0 + ps0;
        l1 = l1 * f1 + ps1;
        m0 = nm0;
        m1 = nm1;
#pragma unroll
        for (int nt = 0; nt < 16; nt++) {
            accO[nt][0] *= f0; accO[nt][1] *= f0;
            accO[nt][2] *= f1; accO[nt][3] *= f1;
        }

#pragma unroll
        for (int ks_ = 0; ks_ < 4; ks_++) {
            uint32_t a[4];
            a[0] = pf[2 * ks_][0];
            a[1] = pf[2 * ks_][1];
            a[2] = pf[2 * ks_ + 1][0];
            a[3] = pf[2 * ks_ + 1][1];
#pragma unroll
            for (int ntb = 0; ntb < 16; ntb += 2) {
                uint32_t vf[4];
                ldsm_x4(vf, vbase_b + voffL + (uint32_t)(ntb * 8 * 36 + 8 * ks_) * 4u);
                mma_fp16(accO[ntb],     a, vf);
                mma_fp16(accO[ntb + 1], a, vf + 2);
            }
        }
        __syncthreads();
        if (kb + 2 < nkb) issue(kb + 2);
        CP_COMMIT();
    }

    const int b_ = bh >> 4;
    const int h_ = bh & 15;
    const float inv0 = 1.0f / l0;
    const float inv1 = 1.0f / l1;
    const int r0g = q0 + rowb + g;
    __half* Op0 = O + ((size_t)b_ * Sc + r0g) * Dc + h_ * HDc;
    __half* Op1 = Op0 + (size_t)8 * Dc;
#pragma unroll
    for (int nt = 0; nt < 16; nt++) {
        const int cc = nt * 8 + 2 * t4;
        *(uint32_t*)&Op0[cc] = h2u(accO[nt][0] * inv0, accO[nt][1] * inv0);
        *(uint32_t*)&Op1[cc] = h2u(accO[nt][2] * inv1, accO[nt][3] * inv1);
    }
}

// ---------------------------------------------------------------------------
extern "C" void kernel_launch(void* const* d_in, const int* in_sizes, int n_in,
                              void* d_out, int out_size)
{
    const float* x  = (const float*)d_in[0];
    const float* wq = (const float*)d_in[1];
    const float* wk = (const float*)d_in[2];
    const float* wv = (const float*)d_in[3];
    const float* wo = (const float*)d_in[4];
    const int* pos  = (const int*)d_in[5];

    __half *xh, *wqh, *wkh, *wvh, *woh, *q, *k, *v, *oh;
    cudaGetSymbolAddress((void**)&xh,  g_xh);
    cudaGetSymbolAddress((void**)&wqh, g_wqh);
    cudaGetSymbolAddress((void**)&wkh, g_wkh);
    cudaGetSymbolAddress((void**)&wvh, g_wvh);
    cudaGetSymbolAddress((void**)&woh, g_woh);
    cudaGetSymbolAddress((void**)&q,   g_Qh);
    cudaGetSymbolAddress((void**)&k,   g_Kh);
    cudaGetSymbolAddress((void**)&v,   g_Vh);
    cudaGetSymbolAddress((void**)&oh,  g_Oh);

    // One launch converts all five fp32 tensors to fp16
    f2h_all<<<32768, 256>>>(x, wq, wk, wv, wo, xh, wqh, wkh, wvh, woh);

    cudaFuncSetAttribute(gemm_qkv, cudaFuncAttributeMaxDynamicSharedMemorySize, GSMEMB);
    cudaFuncSetAttribute(gemm_out, cudaFuncAttributeMaxDynamicSharedMemorySize, GSMEMB);
    cudaFuncSetAttribute(attn_mma, cudaFuncAttributeMaxDynamicSharedMemorySize, ATT_SMEMB);

    // Merged Q/K/V projections (256 threads, epilogue-light config)
    gemm_qkv<<<dim3(Dc / 128, Mc / 128, 3), 256, GSMEMB>>>(
        xh, wqh, wkh, wvh, q, k, v, pos);

    attn_mma<<<dim3(Sc / 128, Bc * Hc), 256, ATT_SMEMB>>>(q, k, v, oh);

    // Output projection (128 threads, 64x64 warp tiles)
    gemm_out<<<dim3(Dc / 128, Mc / 128), 128, GSMEMB>>>(oh, woh, (float*)d_out);
}

// round 16
// speedup vs baseline: 1.0852x; 1.0316x over previous
#include <cuda_runtime.h>
#include <cuda_fp16.h>
#include <math.h>
#include <stdint.h>

// Problem dims
constexpr int Bc = 4, Sc = 2048, Dc = 2048, Hc = 16, HDc = 128;
constexpr int Mc = Bc * Sc;

// Scratch (fp16 everywhere between stages)
__device__ __half g_xh [Mc * Dc];
__device__ __half g_wqh[Dc * Dc];
__device__ __half g_wkh[Dc * Dc];
__device__ __half g_wvh[Dc * Dc];
__device__ __half g_woh[Dc * Dc];
__device__ __half g_Qh [Bc * Hc * Sc * HDc]; // [B,H,S,HD], pre-scaled 1/sqrt(HD)
__device__ __half g_Kh [Bc * Hc * Sc * HDc]; // [B,H,S,HD]
__device__ __half g_Vh [Bc * Hc * Sc * HDc]; // [B,H,HD,S] (TRANSPOSED per head)
__device__ __half g_Oh [Mc * Dc];            // attention output [B,S,D] fp16
__device__ float2 g_rope[Sc * 64];           // (cos, sin) per (s, pair-index)

// ---------------------------------------------------------------------------
// helpers
// ---------------------------------------------------------------------------
__device__ __forceinline__ void mma_fp16(float* d, const uint32_t* a, const uint32_t* b) {
    asm volatile(
        "mma.sync.aligned.m16n8k16.row.col.f32.f16.f16.f32 "
        "{%0,%1,%2,%3},{%4,%5,%6,%7},{%8,%9},{%0,%1,%2,%3};"
        : "+f"(d[0]), "+f"(d[1]), "+f"(d[2]), "+f"(d[3])
        : "r"(a[0]), "r"(a[1]), "r"(a[2]), "r"(a[3]), "r"(b[0]), "r"(b[1]));
}

__device__ __forceinline__ void ldsm_x4(uint32_t* r, uint32_t addr) {
    asm volatile("ldmatrix.sync.aligned.m8n8.x4.shared.b16 {%0,%1,%2,%3}, [%4];"
        : "=r"(r[0]), "=r"(r[1]), "=r"(r[2]), "=r"(r[3]) : "r"(addr));
}

__device__ __forceinline__ uint32_t h2u(float x, float y) {
    __half2 h = __float22half2_rn(make_float2(x, y));
    return *(uint32_t*)&h;
}

__device__ __forceinline__ uint32_t smem_u32(const void* p) {
    uint32_t a;
    asm("{ .reg .u64 t; cvta.to.shared.u64 t, %1; cvt.u32.u64 %0, t; }"
        : "=r"(a) : "l"(p));
    return a;
}

#define CP_ASYNC16(dst, src) \
    asm volatile("cp.async.cg.shared.global [%0], [%1], 16;" :: "r"(dst), "l"(src))
#define CP_COMMIT() asm volatile("cp.async.commit_group;" ::: "memory")
#define CP_WAIT1()  asm volatile("cp.async.wait_group 1;" ::: "memory")
#define CP_WAIT0()  asm volatile("cp.async.wait_group 0;" ::: "memory")

// ---------------------------------------------------------------------------
// fp32 -> fp16 conversion: ALL five tensors in ONE launch.
// ---------------------------------------------------------------------------
__global__ void f2h_all(const float* __restrict__ x,  const float* __restrict__ wq,
                        const float* __restrict__ wk, const float* __restrict__ wv,
                        const float* __restrict__ wo,
                        __half* xh, __half* wqh, __half* wkh, __half* wvh, __half* woh)
{
    const int i = blockIdx.x * 256 + threadIdx.x;
    const float* in;
    __half* out;
    int idx;
    if (i < 4194304) {
        in = x; out = xh; idx = i;
    } else {
        const int j = i - 4194304;
        const int r = j >> 20;
        idx = j & 0xFFFFF;
        in  = (r == 0) ? wq  : (r == 1) ? wk  : (r == 2) ? wv  : wo;
        out = (r == 0) ? wqh : (r == 1) ? wkh : (r == 2) ? wvh : woh;
    }
    float4 v = ((const float4*)in)[idx];
    uint2 o;
    o.x = h2u(v.x, v.y);
    o.y = h2u(v.z, v.w);
    ((uint2*)out)[idx] = o;
}

// ---------------------------------------------------------------------------
// RoPE table: g_rope[s*64 + j] = (cos, sin) of (float)pos[s] * invf(2j),
// computed with EXPRESSIONS IDENTICAL to the previous in-epilogue code
// -> bitwise identical rotation results.
// ---------------------------------------------------------------------------
__global__ void rope_tab(const int* __restrict__ pos)
{
    const int i = blockIdx.x * 256 + threadIdx.x;   // 0..131071
    const int s = i >> 6;
    const int j = i & 63;
    const float invf = (float)exp2(-(double)(2 * j) * (13.287712379549449 / 128.0));
    const float ang = (float)pos[s] * invf;
    float sn, cs;
    sincosf(ang, &sn, &cs);
    g_rope[i] = make_float2(cs, sn);
}

// ---------------------------------------------------------------------------
// Shared GEMM constants: CTA 128x128, k-depth 32, 3-stage cp.async ring.
// smem row stride 20 u32 (ldsm banks conflict-free).
// ---------------------------------------------------------------------------
constexpr int LDSg   = 20;
constexpr int STG_U  = 2 * 128 * LDSg;     // 5120 u32 per stage
constexpr int GSMEMB = 3 * STG_U * 4;      // 61440 B

// ---------------------------------------------------------------------------
// Mainloop: 4 warps / 128 threads, warp tile 64x64 (measured-best tensor util).
// Data placement and k-order identical across rounds -> bitwise stable.
// ---------------------------------------------------------------------------
__device__ __forceinline__ void gemm_main4(const __half* __restrict__ A,
                                           const __half* __restrict__ W,
                                           int bm, int bn,
                                           uint32_t* smu, float (&acc)[4][8][4])
{
    constexpr int Kd = Dc;
    const uint32_t smb = smem_u32(smu);
    const int tid  = threadIdx.x;
    const int wid  = tid >> 5;
    const int lane = tid & 31;
    const int wm   = (wid >> 1) * 64;
    const int wn   = (wid & 1) * 64;

    auto issue_stage = [&](int s, int kt) {
        const uint32_t so = (uint32_t)(s * STG_U);
        const int ko = kt * 32;
#pragma unroll
        for (int p = 0; p < 4; p++) {
            const int q = tid + p * 128;
            const int row = q >> 2;
            const int c4 = q & 3;
            CP_ASYNC16(smb + (uint32_t)(so + row * LDSg + c4 * 4) * 4u,
                       A + (size_t)(bm + row) * Kd + ko + c4 * 8);
            CP_ASYNC16(smb + (uint32_t)(so + 2560 + row * LDSg + c4 * 4) * 4u,
                       W + (size_t)(bn + row) * Kd + ko + c4 * 8);
        }
    };

    const uint32_t aoff = (uint32_t)((wm + (lane & 15)) * LDSg
                                     + ((lane >> 4) & 1) * 4) * 4u;
    const uint32_t boff = (uint32_t)((wn + (lane & 7) + (lane >> 4) * 8) * LDSg
                                     + ((lane >> 3) & 1) * 4) * 4u;

#pragma unroll
    for (int mt = 0; mt < 4; mt++)
#pragma unroll
        for (int nt = 0; nt < 8; nt++)
#pragma unroll
            for (int r = 0; r < 4; r++) acc[mt][nt][r] = 0.0f;

    issue_stage(0, 0); CP_COMMIT();
    issue_stage(1, 1); CP_COMMIT();

    constexpr int NKT = Kd / 32;  // 64
    for (int kt = 0; kt < NKT; kt++) {
        const int s = kt % 3;
        CP_WAIT1();
        __syncthreads();
        if (kt + 2 < NKT) issue_stage((kt + 2) % 3, kt + 2);
        CP_COMMIT();

        const uint32_t abase = smb + (uint32_t)(s * STG_U) * 4u + aoff;
        const uint32_t bbase = smb + (uint32_t)(s * STG_U + 2560) * 4u + boff;
#pragma unroll
        for (int ks = 0; ks < 2; ks++) {
            const uint32_t ko = (uint32_t)(ks * 32);
            uint32_t af[4][4];
            ldsm_x4(af[0], abase + ko);
            ldsm_x4(af[1], abase + ko + 1280u);
            ldsm_x4(af[2], abase + ko + 2560u);
            ldsm_x4(af[3], abase + ko + 3840u);
#pragma unroll
            for (int ntb = 0; ntb < 8; ntb += 2) {
                uint32_t bf[4];
                ldsm_x4(bf, bbase + ko + (uint32_t)(ntb * 640));
#pragma unroll
                for (int mt = 0; mt < 4; mt++) {
                    mma_fp16(acc[mt][ntb],     af[mt], bf);
                    mma_fp16(acc[mt][ntb + 1], af[mt], bf + 2);
                }
            }
        }
    }
}

// ---------------------------------------------------------------------------
// Merged Q/K/V projection (128 threads, 64x64 warp tiles, table-based RoPE).
// z=0: Q (+RoPE, *1/sqrt(HD)) [B,H,S,HD]; z=1: K (+RoPE) [B,H,S,HD];
// z=2: V transposed [B,H,HD,S].
// ---------------------------------------------------------------------------
__global__ void __launch_bounds__(128, 2)
gemm_qkv(const __half* __restrict__ xh,
         const __half* __restrict__ wqh, const __half* __restrict__ wkh,
         const __half* __restrict__ wvh,
         __half* __restrict__ Qo, __half* __restrict__ Ko, __half* __restrict__ Vo)
{
    extern __shared__ uint32_t smu[];
    const int bm = blockIdx.y * 128;
    const int bn = blockIdx.x * 128;
    const int z  = blockIdx.z;
    const __half* W = (z == 0) ? wqh : (z == 1) ? wkh : wvh;

    float acc[4][8][4];
    gemm_main4(xh, W, bm, bn, smu, acc);

    const int tid  = threadIdx.x;
    const int wid  = tid >> 5;
    const int lane = tid & 31;
    const int wm   = (wid >> 1) * 64;
    const int wn   = (wid & 1) * 64;
    const int g    = lane >> 2;
    const int t4   = lane & 3;

    const float qscale = 0.08838834764831845f;  // 1/sqrt(128)
    __half* oh = (z == 0) ? Qo : (z == 1) ? Ko : Vo;

#pragma unroll
    for (int nt = 0; nt < 8; nt++) {
        const int col = bn + wn + nt * 8 + 2 * t4;
        const int h  = col >> 7;
        const int hd = col & 127;
        const int jr = hd >> 1;            // rope pair index
#pragma unroll
        for (int mt = 0; mt < 4; mt++) {
#pragma unroll
            for (int rr = 0; rr < 2; rr++) {
                const int m = bm + wm + mt * 16 + g + rr * 8;
                const int b = m >> 11;
                const int s = m & 2047;
                float x1 = acc[mt][nt][rr * 2];
                float x2 = acc[mt][nt][rr * 2 + 1];
                if (z <= 1) {
                    const float2 cssn = g_rope[s * 64 + jr];
                    float r1 = x1 * cssn.x - x2 * cssn.y;
                    float r2 = x1 * cssn.y + x2 * cssn.x;
                    if (z == 0) { r1 *= qscale; r2 *= qscale; }
                    *(uint32_t*)&oh[(((size_t)b * Hc + h) * Sc + s) * HDc + hd] =
                        h2u(r1, r2);
                } else {
                    const size_t base = ((size_t)b * Hc + h) * HDc;
                    oh[(base + hd)     * Sc + s] = __float2half_rn(x1);
                    oh[(base + hd + 1) * Sc + s] = __float2half_rn(x2);
                }
            }
        }
    }
}

// ---------------------------------------------------------------------------
// Output projection (128 threads, 64x64 warp tiles): out fp32 = O * wo^T
// ---------------------------------------------------------------------------
__global__ void __launch_bounds__(128, 2)
gemm_out(const __half* __restrict__ Oh, const __half* __restrict__ woh,
         float* __restrict__ out)
{
    extern __shared__ uint32_t smu[];
    const int bm = blockIdx.y * 128;
    const int bn = blockIdx.x * 128;

    float acc[4][8][4];
    gemm_main4(Oh, woh, bm, bn, smu, acc);

    const int tid  = threadIdx.x;
    const int wid  = tid >> 5;
    const int lane = tid & 31;
    const int wm   = (wid >> 1) * 64;
    const int wn   = (wid & 1) * 64;
    const int g    = lane >> 2;
    const int t4   = lane & 3;

#pragma unroll
    for (int nt = 0; nt < 8; nt++) {
        const int col = bn + wn + nt * 8 + 2 * t4;
#pragma unroll
        for (int mt = 0; mt < 4; mt++) {
            const int r0 = bm + wm + mt * 16 + g;
            *(float2*)&out[(size_t)r0 * Dc + col] =
                make_float2(acc[mt][nt][0], acc[mt][nt][1]);
            *(float2*)&out[(size_t)(r0 + 8) * Dc + col] =
                make_float2(acc[mt][nt][2], acc[mt][nt][3]);
        }
    }
}

// ---------------------------------------------------------------------------
// Flash attention (causal), fp16 m16n8k16, cp.async 2-stage K/V.
// Register-resident P + ldmatrix B-fragments (round-11 proven, unchanged).
// ---------------------------------------------------------------------------
constexpr int KSTG_U    = 8960;
constexpr int VOFF_U    = 4352;
constexpr int ATT_SMEMB = 2 * KSTG_U * 4;   // 71680 B

__global__ void __launch_bounds__(256, 1)
attn_mma(const __half* __restrict__ Q, const __half* __restrict__ K,
         const __half* __restrict__ V, __half* __restrict__ O)
{
    extern __shared__ uint32_t smu[];
    const uint32_t smb = smem_u32(smu);

    const int tid  = threadIdx.x;
    const int wid  = tid >> 5;
    const int lane = tid & 31;
    const int g    = lane >> 2;
    const int t4   = lane & 3;
    const int qb   = (gridDim.x - 1) - blockIdx.x;   // heavy blocks first
    const int bh   = blockIdx.y;
    const int q0   = qb * 128;
    const size_t hoff = (size_t)bh * (size_t)(Sc * HDc);
    const int rowb = wid * 16;

    const int ntL  = lane >> 4;
    const int kbL  = (lane >> 3) & 1;
    const int rowL = lane & 7;
    const uint32_t koffL = (uint32_t)((ntL * 8 + rowL) * 68 + 4 * kbL) * 4u;
    const uint32_t voffL = (uint32_t)((ntL * 8 + rowL) * 36 + 4 * kbL) * 4u;

    {
        const __half* Qg = Q + hoff + (size_t)q0 * HDc;
#pragma unroll
        for (int p = 0; p < 8; p++) {
            int q = tid + p * 256;
            int row = q >> 4;
            int c4 = q & 15;
            CP_ASYNC16(smb + (uint32_t)(row * 68 + c4 * 4) * 4u,
                       Qg + (size_t)row * HDc + c4 * 8);
        }
        CP_COMMIT();
        CP_WAIT0();
    }
    __syncthreads();

    uint32_t qf[8][4];
#pragma unroll
    for (int ks = 0; ks < 8; ks++) {
        const int r0 = (rowb + g) * 68 + 8 * ks + t4;
        const int r1 = r0 + 8 * 68;
        qf[ks][0] = smu[r0];
        qf[ks][1] = smu[r1];
        qf[ks][2] = smu[r0 + 4];
        qf[ks][3] = smu[r1 + 4];
    }
    __syncthreads();

    const int nkb = 2 * qb + 2;

    auto issue = [&](int kb) {
        const int s = kb & 1;
        const __half* Kg = K + hoff + (size_t)(kb * 64) * HDc;
        const __half* Vg = V + hoff + (size_t)kb * 64;
        const uint32_t kbase = smb + (uint32_t)(s * KSTG_U) * 4u;
        const uint32_t vbase = kbase + (uint32_t)VOFF_U * 4u;
#pragma unroll
        for (int p = 0; p < 4; p++) {
            int q = tid + p * 256;
            int row = q >> 4;
            int c4 = q & 15;
            CP_ASYNC16(kbase + (uint32_t)(row * 68 + c4 * 4) * 4u,
                       Kg + (size_t)row * HDc + c4 * 8);
        }
#pragma unroll
        for (int p = 0; p < 4; p++) {
            int q = tid + p * 256;
            int row = q >> 3;
            int c4 = q & 7;
            CP_ASYNC16(vbase + (uint32_t)(row * 36 + c4 * 4) * 4u,
                       Vg + (size_t)row * Sc + c4 * 8);
        }
    };

    float accO[16][4];
#pragma unroll
    for (int nt = 0; nt < 16; nt++)
#pragma unroll
        for (int r = 0; r < 4; r++) accO[nt][r] = 0.0f;
    float m0 = -1e30f, m1 = -1e30f, l0 = 0.0f, l1 = 0.0f;

    issue(0); CP_COMMIT();
    if (nkb > 1) issue(1);
    CP_COMMIT();

    for (int kb = 0; kb < nkb; kb++) {
        CP_WAIT1();
        __syncthreads();
        const uint32_t kbase_b = smb + (uint32_t)((kb & 1) * KSTG_U) * 4u;
        const uint32_t vbase_b = kbase_b + (uint32_t)VOFF_U * 4u;

        float s[8][4];
#pragma unroll
        for (int nt = 0; nt < 8; nt++)
#pragma unroll
            for (int r = 0; r < 4; r++) s[nt][r] = 0.0f;

#pragma unroll
        for (int ks_ = 0; ks_ < 8; ks_++) {
#pragma unroll
            for (int ntb = 0; ntb < 8; ntb += 2) {
                uint32_t kf[4];
                ldsm_x4(kf, kbase_b + koffL + (uint32_t)(ntb * 8 * 68 + 8 * ks_) * 4u);
                mma_fp16(s[ntb],     qf[ks_], kf);
                mma_fp16(s[ntb + 1], qf[ks_], kf + 2);
            }
        }

        if (kb >= 2 * qb) {
            const int colb = kb * 64 + 2 * t4;
            const int row0 = q0 + rowb + g;
#pragma unroll
            for (int nt = 0; nt < 8; nt++) {
                const int c0 = colb + nt * 8;
                if (c0     > row0)     s[nt][0] = -1e30f;
                if (c0 + 1 > row0)     s[nt][1] = -1e30f;
                if (c0     > row0 + 8) s[nt][2] = -1e30f;
                if (c0 + 1 > row0 + 8) s[nt][3] = -1e30f;
            }
        }

        float bm0 = -1e30f, bm1 = -1e30f;
#pragma unroll
        for (int nt = 0; nt < 8; nt++) {
            bm0 = fmaxf(bm0, fmaxf(s[nt][0], s[nt][1]));
            bm1 = fmaxf(bm1, fmaxf(s[nt][2], s[nt][3]));
        }
        bm0 = fmaxf(bm0, __shfl_xor_sync(0xffffffffu, bm0, 1));
        bm0 = fmaxf(bm0, __shfl_xor_sync(0xffffffffu, bm0, 2));
        bm1 = fmaxf(bm1, __shfl_xor_sync(0xffffffffu, bm1, 1));
        bm1 = fmaxf(bm1, __shfl_xor_sync(0xffffffffu, bm1, 2));
        const float nm0 = fmaxf(m0, bm0);
        const float nm1 = fmaxf(m1, bm1);
        const float f0 = __expf(m0 - nm0);
        const float f1 = __expf(m1 - nm1);
        float ps0 = 0.0f, ps1 = 0.0f;
        uint32_t pf[8][2];
#pragma unroll
        for (int nt = 0; nt < 8; nt++) {
            float p0 = __expf(s[nt][0] - nm0);
            float p1 = __expf(s[nt][1] - nm0);
            float p2 = __expf(s[nt][2] - nm1);
            float p3 = __expf(s[nt][3] - nm1);
            ps0 += p0 + p1;
            ps1 += p2 + p3;
            pf[nt][0] = h2u(p0, p1);
            pf[nt][1] = h2u(p2, p3);
        }
        ps0 += __shfl_xor_sync(0xffffffffu, ps0, 1);
        ps0 += __shfl_xor_sync(0xffffffffu, ps0, 2);
        ps1 += __shfl_xor_sync(0xffffffffu, ps1, 1);
        ps1 += __shfl_xor_sync(0xffffffffu, ps1, 2);
        l0 = l0 * f0 + ps0;
        l1 = l1 * f1 + ps1;
        m0 = nm0;
        m1 = nm1;
#pragma unroll
        for (int nt = 0; nt < 16; nt++) {
            accO[nt][0] *= f0; accO[nt][1] *= f0;
            accO[nt][2] *= f1; accO[nt][3] *= f1;
        }

#pragma unroll
        for (int ks_ = 0; ks_ < 4; ks_++) {
            uint32_t a[4];
            a[0] = pf[2 * ks_][0];
            a[1] = pf[2 * ks_][1];
            a[2] = pf[2 * ks_ + 1][0];
            a[3] = pf[2 * ks_ + 1][1];
#pragma unroll
            for (int ntb = 0; ntb < 16; ntb += 2) {
                uint32_t vf[4];
                ldsm_x4(vf, vbase_b + voffL + (uint32_t)(ntb * 8 * 36 + 8 * ks_) * 4u);
                mma_fp16(accO[ntb],     a, vf);
                mma_fp16(accO[ntb + 1], a, vf + 2);
            }
        }
        __syncthreads();
        if (kb + 2 < nkb) issue(kb + 2);
        CP_COMMIT();
    }

    const int b_ = bh >> 4;
    const int h_ = bh & 15;
    const float inv0 = 1.0f / l0;
    const float inv1 = 1.0f / l1;
    const int r0g = q0 + rowb + g;
    __half* Op0 = O + ((size_t)b_ * Sc + r0g) * Dc + h_ * HDc;
    __half* Op1 = Op0 + (size_t)8 * Dc;
#pragma unroll
    for (int nt = 0; nt < 16; nt++) {
        const int cc = nt * 8 + 2 * t4;
        *(uint32_t*)&Op0[cc] = h2u(accO[nt][0] * inv0, accO[nt][1] * inv0);
        *(uint32_t*)&Op1[cc] = h2u(accO[nt][2] * inv1, accO[nt][3] * inv1);
    }
}

// ---------------------------------------------------------------------------
extern "C" void kernel_launch(void* const* d_in, const int* in_sizes, int n_in,
                              void* d_out, int out_size)
{
    const float* x  = (const float*)d_in[0];
    const float* wq = (const float*)d_in[1];
    const float* wk = (const float*)d_in[2];
    const float* wv = (const float*)d_in[3];
    const float* wo = (const float*)d_in[4];
    const int* pos  = (const int*)d_in[5];

    __half *xh, *wqh, *wkh, *wvh, *woh, *q, *k, *v, *oh;
    cudaGetSymbolAddress((void**)&xh,  g_xh);
    cudaGetSymbolAddress((void**)&wqh, g_wqh);
    cudaGetSymbolAddress((void**)&wkh, g_wkh);
    cudaGetSymbolAddress((void**)&wvh, g_wvh);
    cudaGetSymbolAddress((void**)&woh, g_woh);
    cudaGetSymbolAddress((void**)&q,   g_Qh);
    cudaGetSymbolAddress((void**)&k,   g_Kh);
    cudaGetSymbolAddress((void**)&v,   g_Vh);
    cudaGetSymbolAddress((void**)&oh,  g_Oh);

    // Conversions + RoPE table (independent small launches)
    f2h_all<<<32768, 256>>>(x, wq, wk, wv, wo, xh, wqh, wkh, wvh, woh);
    rope_tab<<<512, 256>>>(pos);

    cudaFuncSetAttribute(gemm_qkv, cudaFuncAttributeMaxDynamicSharedMemorySize, GSMEMB);
    cudaFuncSetAttribute(gemm_out, cudaFuncAttributeMaxDynamicSharedMemorySize, GSMEMB);
    cudaFuncSetAttribute(attn_mma, cudaFuncAttributeMaxDynamicSharedMemorySize, ATT_SMEMB);

    // Merged Q/K/V projections (128 threads, 64x64 warp tiles, table RoPE)
    gemm_qkv<<<dim3(Dc / 128, Mc / 128, 3), 128, GSMEMB>>>(
        xh, wqh, wkh, wvh, q, k, v);

    attn_mma<<<dim3(Sc / 128, Bc * Hc), 256, ATT_SMEMB>>>(q, k, v, oh);

    // Output projection (128 threads, 64x64 warp tiles)
    gemm_out<<<dim3(Dc / 128, Mc / 128), 128, GSMEMB>>>(oh, woh, (float*)d_out);
}